// round 5
// baseline (speedup 1.0000x reference)
#include <cuda_runtime.h>

#define HIDDEN 128
#define THREADS 256
#define GRID 592          // 4 blocks per SM exactly (148 SMs), single wave
#define TILE_RAYS 512     // 256 threads x 2 rays

typedef unsigned long long ull;

__device__ __forceinline__ float ex2f_(float x) {
    float y; asm("ex2.approx.f32 %0, %1;" : "=f"(y) : "f"(x)); return y;
}
__device__ __forceinline__ ull pk2(float lo, float hi) {
    ull r; asm("mov.b64 %0, {%1, %2};" : "=l"(r) : "f"(lo), "f"(hi)); return r;
}
__device__ __forceinline__ void upk2(ull v, float& lo, float& hi) {
    asm("mov.b64 {%0, %1}, %2;" : "=f"(lo), "=f"(hi) : "l"(v));
}
__device__ __forceinline__ ull ffma2(ull a, ull b, ull c) {
    ull d; asm("fma.rn.f32x2 %0, %1, %2, %3;" : "=l"(d) : "l"(a), "l"(b), "l"(c)); return d;
}
__device__ __forceinline__ ull fmul2(ull a, ull b) {
    ull d; asm("mul.rn.f32x2 %0, %1, %2;" : "=l"(d) : "l"(a), "l"(b)); return d;
}

// Degree-5 poly for ln(1+e), e in [0,1], direct powers of e.
// Derived from the verified deg-6 u-poly by exact T6 economization
// (err += 8.3e-6, total ~1.2e-5) and exact binomial re-expansion.
// Endpoint-verified: p(0)=1.2e-5, p(0.5)=ln1.5-8e-6, p(1)=ln2+8.5e-6.
#define PC0  0.0000121584f
#define PC1  0.9992069636f
#define PC2 -0.4901088568f
#define PC3  0.2850514088f
#define PC4 -0.1314078224f
#define PC5  0.0304018720f

// 48-byte weight record: three LDS.128 at immediate offsets 0/16/32.
struct __align__(16) W48 {
    ull w0, w1, w2, b;    // W1 rows + b1, pre-scaled by log2(e), dup {w,w}
    ull w2p;              // {W2, W2}
    float w2l;            // W2 * ln2 (scalar)
    float pad;
};

__global__ __launch_bounds__(THREADS, 4)
void raymarch_kernel(const float* __restrict__ r,
                     const float* __restrict__ pivot,
                     const float* __restrict__ W1,
                     const float* __restrict__ b1,
                     const float* __restrict__ W2,
                     const float* __restrict__ b2,
                     const int*   __restrict__ n_iter_p,
                     float* __restrict__ out,
                     int n_rays)
{
    __shared__ W48 s_w[HIDDEN];   // 6 KB

    const float L2E = 1.4426950408889634f;
    const float LN2 = 0.6931471805599453f;

    const int tid = threadIdx.x;
    if (tid < HIDDEN) {
        float a0 = W1[tid] * L2E;
        float a1 = W1[HIDDEN + tid] * L2E;
        float a2 = W1[2 * HIDDEN + tid] * L2E;
        float bb = b1[tid] * L2E;
        float w2 = W2[tid];
        s_w[tid].w0  = pk2(a0, a0);
        s_w[tid].w1  = pk2(a1, a1);
        s_w[tid].w2  = pk2(a2, a2);
        s_w[tid].b   = pk2(bb, bb);
        s_w[tid].w2p = pk2(w2, w2);
        s_w[tid].w2l = w2 * LN2;
        s_w[tid].pad = 0.f;
    }
    __syncthreads();

    const float pv0 = pivot[0], pv1 = pivot[1], pv2 = pivot[2];
    const float b2v = b2[0];
    const int n_it = n_iter_p ? *n_iter_p : 20;
    const int ntiles = (n_rays + TILE_RAYS - 1) / TILE_RAYS;

    const ull C0 = pk2(PC0, PC0), C1 = pk2(PC1, PC1), C2 = pk2(PC2, PC2),
              C3 = pk2(PC3, PC3), C4 = pk2(PC4, PC4), C5 = pk2(PC5, PC5);

    for (int t = blockIdx.x; t < ntiles; t += GRID) {
        const int base = t * TILE_RAYS + tid * 2;
        const bool valid = (base + 1 < n_rays) && (base >= 0);

        float4 rv0 = valid ? reinterpret_cast<const float4*>(r)[base]
                           : make_float4(1.f, 0.f, 0.f, 0.f);
        float4 rv1 = valid ? reinterpret_cast<const float4*>(r)[base + 1]
                           : make_float4(1.f, 0.f, 0.f, 0.f);

        float inv0 = rsqrtf(rv0.x*rv0.x + rv0.y*rv0.y + rv0.z*rv0.z + rv0.w*rv0.w);
        float inv1 = rsqrtf(rv1.x*rv1.x + rv1.y*rv1.y + rv1.z*rv1.z + rv1.w*rv1.w);
        float rn0_0 = rv0.x*inv0, dx0 = rv0.y*inv0, dy0 = rv0.z*inv0, dz0 = rv0.w*inv0;
        float rn0_1 = rv1.x*inv1, dx1 = rv1.y*inv1, dy1 = rv1.z*inv1, dz1 = rv1.w*inv1;

        float alpha0 = 0.f, alpha1 = 0.f;

        for (int it = 0; it < n_it; ++it) {
            ull p0d = pk2(fmaf(alpha0, dx0, pv0), fmaf(alpha1, dx1, pv0));
            ull p1d = pk2(fmaf(alpha0, dy0, pv1), fmaf(alpha1, dy1, pv1));
            ull p2d = pk2(fmaf(alpha0, dz0, pv2), fmaf(alpha1, dz1, pv2));
            float x0_0 = alpha0 * rn0_0;
            float x0_1 = alpha1 * rn0_1;

            ull accP = 0ull;
            float accM0 = 0.f, accM1 = 0.f;

            #pragma unroll 4
            for (int j = 0; j < HIDDEN; ++j) {
                ulonglong2 q0 = *reinterpret_cast<const ulonglong2*>(&s_w[j].w0);   // w0,w1
                ulonglong2 q1 = *reinterpret_cast<const ulonglong2*>(&s_w[j].w2);   // w2,b
                ulonglong2 q2 = *reinterpret_cast<const ulonglong2*>(&s_w[j].w2p);  // w2p,{w2l,pad}
                float w2l, dummy; upk2(q2.y, w2l, dummy);

                // aL = (x . W1 + b1) * log2e, packed over 2 rays
                ull aL = ffma2(p0d, q0.x, ffma2(p1d, q0.y, ffma2(p2d, q1.x, q1.y)));
                float alo, ahi; upk2(aL, alo, ahi);

                // e = 2^(-|aL|) = exp(-|arg|)  (neg-abs folds into MUFU operand)
                float elo = ex2f_(-fabsf(alo));
                float ehi = ex2f_(-fabsf(ahi));
                ull e2 = pk2(elo, ehi);

                // ln(1+e): degree-5 Estrin (depth 3 FFMA2 after e)
                ull em = fmul2(e2, e2);
                ull t0 = ffma2(C1, e2, C0);
                ull t1 = ffma2(C3, e2, C2);
                ull t2 = ffma2(C5, e2, C4);
                ull pp = ffma2(t2, em, t1);
                pp = ffma2(pp, em, t0);
                accP = ffma2(q2.x, pp, accP);        // W2 * ln(1+e)

                // relu part, scalar per lane (no packing movs)
                accM0 = fmaf(w2l, fmaxf(alo, 0.f), accM0);
                accM1 = fmaf(w2l, fmaxf(ahi, 0.f), accM1);
            }

            float pl, ph; upk2(accP, pl, ph);
            float s0 = (pl + accM0) + b2v;
            float s1 = (ph + accM1) + b2v;

            float a0 = fabsf(s0);
            float a1 = fabsf(s1);
            float ext0 = fmaxf(fmaxf(s0, x0_0 - a0), -a0 - x0_0);
            float ext1 = fmaxf(fmaxf(s1, x0_1 - a1), -a1 - x0_1);
            alpha0 -= ext0;
            alpha1 -= ext1;
        }

        if (valid) {
            out[3 * base + 0] = fmaf(alpha0, dx0, pv0);
            out[3 * base + 1] = fmaf(alpha0, dy0, pv1);
            out[3 * base + 2] = fmaf(alpha0, dz0, pv2);
            out[3 * base + 3] = fmaf(alpha1, dx1, pv0);
            out[3 * base + 4] = fmaf(alpha1, dy1, pv1);
            out[3 * base + 5] = fmaf(alpha1, dz1, pv2);
        }
    }
}

extern "C" void kernel_launch(void* const* d_in, const int* in_sizes, int n_in,
                              void* d_out, int out_size)
{
    const float* r     = (const float*)d_in[0];
    const float* pivot = (const float*)d_in[1];
    const float* W1    = (const float*)d_in[2];
    const float* b1    = (const float*)d_in[3];
    const float* W2    = (const float*)d_in[4];
    const float* b2    = (const float*)d_in[5];
    const int*   n_it  = (n_in > 6) ? (const int*)d_in[6] : nullptr;

    const int n_rays = in_sizes[0] / 4;

    raymarch_kernel<<<GRID, THREADS>>>(r, pivot, W1, b1, W2, b2, n_it,
                                       (float*)d_out, n_rays);
}

// round 6
// speedup vs baseline: 1.3186x; 1.3186x over previous
#include <cuda_runtime.h>

#define HIDDEN 128
#define THREADS 256
#define RPT 2   // rays per thread, packed as one f32x2 lane-pair

typedef unsigned long long ull;

__device__ __forceinline__ float ex2f_(float x) {
    float y; asm("ex2.approx.f32 %0, %1;" : "=f"(y) : "f"(x)); return y;
}
__device__ __forceinline__ ull pk2(float lo, float hi) {
    ull r; asm("mov.b64 %0, {%1, %2};" : "=l"(r) : "f"(lo), "f"(hi)); return r;
}
__device__ __forceinline__ void upk2(ull v, float& lo, float& hi) {
    asm("mov.b64 {%0, %1}, %2;" : "=f"(lo), "=f"(hi) : "l"(v));
}
__device__ __forceinline__ ull ffma2(ull a, ull b, ull c) {
    ull d; asm("fma.rn.f32x2 %0, %1, %2, %3;" : "=l"(d) : "l"(a), "l"(b), "l"(c)); return d;
}

// Degree-4 poly for ln(1+e), e in [0,1], Horner in e.
// Derivation: Taylor of ln(1.5 + u/2) to deg 8 (u=2e-1), Chebyshev
// economization 8->4 (errors 1.5e-7, 1.0e-6, 8.3e-6, 5.9e-5), exact binomial
// re-expansion in e. Max abs err ~7.5e-5.
// Verified: p(0)=7.6e-5, p(0.25)=ln1.25+3.8e-5, p(0.5)=ln1.5-8.3e-6, p(1)=ln2-5.6e-5.
#define PD0  0.0000761000f
#define PD1  0.9961992000f
#define PD2 -0.4662686000f
#define PD3  0.2184881600f
#define PD4 -0.0554032000f

struct __align__(16) WPack {
    ull w0, w1, w2, b;   // W1 rows + b1, pre-scaled by log2(e), duplicated {w,w}
};

__global__ __launch_bounds__(THREADS, 6)
void raymarch_kernel(const float* __restrict__ r,
                     const float* __restrict__ pivot,
                     const float* __restrict__ W1,
                     const float* __restrict__ b1,
                     const float* __restrict__ W2,
                     const float* __restrict__ b2,
                     const int*   __restrict__ n_iter_p,
                     float* __restrict__ out,
                     int n_rays)
{
    __shared__ WPack s_w[HIDDEN];    // 4 KB
    __shared__ ull   s_w2[HIDDEN];   // 1 KB, {W2, W2}

    const float L2E = 1.4426950408889634f;  // log2(e)

    const int tid = threadIdx.x;
    if (tid < HIDDEN) {
        float a0 = W1[tid] * L2E;
        float a1 = W1[HIDDEN + tid] * L2E;
        float a2 = W1[2 * HIDDEN + tid] * L2E;
        float bb = b1[tid] * L2E;
        float w2 = W2[tid];
        s_w[tid].w0 = pk2(a0, a0);
        s_w[tid].w1 = pk2(a1, a1);
        s_w[tid].w2 = pk2(a2, a2);
        s_w[tid].b  = pk2(bb, bb);
        s_w2[tid]   = pk2(w2, w2);
    }
    __syncthreads();

    const float pv0 = pivot[0], pv1 = pivot[1], pv2 = pivot[2];
    const float b2v = b2[0];
    const int n_it = n_iter_p ? *n_iter_p : 20;

    const int base = (blockIdx.x * THREADS + tid) * RPT;
    const bool valid = (base + 1 < n_rays);

    float4 rv0 = valid ? reinterpret_cast<const float4*>(r)[base]
                       : make_float4(1.f, 0.f, 0.f, 0.f);
    float4 rv1 = valid ? reinterpret_cast<const float4*>(r)[base + 1]
                       : make_float4(1.f, 0.f, 0.f, 0.f);

    float inv0 = rsqrtf(rv0.x * rv0.x + rv0.y * rv0.y + rv0.z * rv0.z + rv0.w * rv0.w);
    float inv1 = rsqrtf(rv1.x * rv1.x + rv1.y * rv1.y + rv1.z * rv1.z + rv1.w * rv1.w);
    float rn0_0 = rv0.x * inv0, dx0 = rv0.y * inv0, dy0 = rv0.z * inv0, dz0 = rv0.w * inv0;
    float rn0_1 = rv1.x * inv1, dx1 = rv1.y * inv1, dy1 = rv1.z * inv1, dz1 = rv1.w * inv1;

    float alpha0 = 0.f, alpha1 = 0.f;

    // Packed constants in registers (10 regs for coeffs + 2 for LN2P).
    const ull C0 = pk2(PD0, PD0), C1 = pk2(PD1, PD1), C2 = pk2(PD2, PD2),
              C3 = pk2(PD3, PD3), C4 = pk2(PD4, PD4);
    const ull LN2P = pk2(0.6931471805599453f, 0.6931471805599453f);

    for (int it = 0; it < n_it; ++it) {
        // Sample point, packed across the 2 rays.
        ull p0d = pk2(fmaf(alpha0, dx0, pv0), fmaf(alpha1, dx1, pv0));
        ull p1d = pk2(fmaf(alpha0, dy0, pv1), fmaf(alpha1, dy1, pv1));
        ull p2d = pk2(fmaf(alpha0, dz0, pv2), fmaf(alpha1, dz1, pv2));
        float x0_0 = alpha0 * rn0_0;
        float x0_1 = alpha1 * rn0_1;

        ull acc = 0ull;   // packed {0.f, 0.f}

        #pragma unroll 4
        for (int j = 0; j < HIDDEN; ++j) {
            const ulonglong2* wp = reinterpret_cast<const ulonglong2*>(&s_w[j]);
            ulonglong2 q0 = wp[0];   // w0, w1
            ulonglong2 q1 = wp[1];   // w2, b
            ull w2d = s_w2[j];

            // aL = (x . W1 + b1) * log2e, packed over 2 rays
            ull aL = ffma2(p0d, q0.x, ffma2(p1d, q0.y, ffma2(p2d, q1.x, q1.y)));
            float alo, ahi; upk2(aL, alo, ahi);

            // e = 2^(-|aL|) = exp(-|a|), per lane (MUFU)
            float elo = ex2f_(-fabsf(alo));
            float ehi = ex2f_(-fabsf(ahi));
            ull e2 = pk2(elo, ehi);

            // ln(1+e): degree-4 Horner in e
            ull p = ffma2(C4, e2, C3);
            p = ffma2(p, e2, C2);
            p = ffma2(p, e2, C1);
            p = ffma2(p, e2, C0);

            // softplus = ln2*max(aL,0) + ln(1+e); accumulate with W2
            ull m = pk2(fmaxf(alo, 0.f), fmaxf(ahi, 0.f));
            ull t = ffma2(LN2P, m, p);
            acc = ffma2(w2d, t, acc);
        }

        float s0, s1; upk2(acc, s0, s1);
        s0 += b2v;
        s1 += b2v;

        float a0 = fabsf(s0);
        float a1 = fabsf(s1);
        float ext0 = fmaxf(fmaxf(s0, x0_0 - a0), -a0 - x0_0);
        float ext1 = fmaxf(fmaxf(s1, x0_1 - a1), -a1 - x0_1);
        alpha0 -= ext0;
        alpha1 -= ext1;
    }

    if (valid) {
        out[3 * base + 0] = fmaf(alpha0, dx0, pv0);
        out[3 * base + 1] = fmaf(alpha0, dy0, pv1);
        out[3 * base + 2] = fmaf(alpha0, dz0, pv2);
        out[3 * base + 3] = fmaf(alpha1, dx1, pv0);
        out[3 * base + 4] = fmaf(alpha1, dy1, pv1);
        out[3 * base + 5] = fmaf(alpha1, dz1, pv2);
    }
}

extern "C" void kernel_launch(void* const* d_in, const int* in_sizes, int n_in,
                              void* d_out, int out_size)
{
    const float* r     = (const float*)d_in[0];
    const float* pivot = (const float*)d_in[1];
    const float* W1    = (const float*)d_in[2];
    const float* b1    = (const float*)d_in[3];
    const float* W2    = (const float*)d_in[4];
    const float* b2    = (const float*)d_in[5];
    const int*   n_it  = (n_in > 6) ? (const int*)d_in[6] : nullptr;

    const int n_rays = in_sizes[0] / 4;
    const int rays_per_block = THREADS * RPT;
    const int blocks = (n_rays + rays_per_block - 1) / rays_per_block;

    raymarch_kernel<<<blocks, THREADS>>>(r, pivot, W1, b1, W2, b2, n_it,
                                         (float*)d_out, n_rays);
}

// round 7
// speedup vs baseline: 1.3262x; 1.0057x over previous
#include <cuda_runtime.h>

#define HIDDEN 128
#define THREADS 256
#define RPT 2   // rays per thread, packed as one f32x2 lane-pair

typedef unsigned long long ull;

__device__ __forceinline__ float ex2f_(float x) {
    float y; asm("ex2.approx.f32 %0, %1;" : "=f"(y) : "f"(x)); return y;
}
__device__ __forceinline__ ull pk2(float lo, float hi) {
    ull r; asm("mov.b64 %0, {%1, %2};" : "=l"(r) : "f"(lo), "f"(hi)); return r;
}
__device__ __forceinline__ void upk2(ull v, float& lo, float& hi) {
    asm("mov.b64 {%0, %1}, %2;" : "=f"(lo), "=f"(hi) : "l"(v));
}
__device__ __forceinline__ ull ffma2(ull a, ull b, ull c) {
    ull d; asm("fma.rn.f32x2 %0, %1, %2, %3;" : "=l"(d) : "l"(a), "l"(b), "l"(c)); return d;
}

// Degree-3 poly for ln(1+e), e in [0,1], Horner in e.
// Derived from the verified deg-4 poly (max err 7.5e-5) by exact shifted-
// Chebyshev economization e^4 = [T4* + 256e^3 - 160e^2 + 32e - 1]/128
// (added err |g4|/128 = 4.33e-4; total ~5.1e-4).
// Verified: p(1) = 0.6935245 = ln2 + 3.8e-4; p(0) = 5.09e-4.
#define PE0  0.0005089380f
#define PE1  0.9823484000f
#define PE2 -0.3970146000f
#define PE3  0.1076817600f

struct __align__(16) WPack {
    ull w0, w1, w2, b;   // W1 rows + b1, pre-scaled by log2(e), duplicated {w,w}
};

__global__ __launch_bounds__(THREADS, 7)
void raymarch_kernel(const float* __restrict__ r,
                     const float* __restrict__ pivot,
                     const float* __restrict__ W1,
                     const float* __restrict__ b1,
                     const float* __restrict__ W2,
                     const float* __restrict__ b2,
                     const int*   __restrict__ n_iter_p,
                     float* __restrict__ out,
                     int n_rays)
{
    __shared__ WPack s_w[HIDDEN];            // 4 KB
    __shared__ ulonglong2 s_w2[HIDDEN];      // 2 KB: {W2,W2}, {W2*ln2, W2*ln2}

    const float L2E = 1.4426950408889634f;  // log2(e)
    const float LN2 = 0.6931471805599453f;

    const int tid = threadIdx.x;
    if (tid < HIDDEN) {
        float a0 = W1[tid] * L2E;
        float a1 = W1[HIDDEN + tid] * L2E;
        float a2 = W1[2 * HIDDEN + tid] * L2E;
        float bb = b1[tid] * L2E;
        float w2 = W2[tid];
        s_w[tid].w0 = pk2(a0, a0);
        s_w[tid].w1 = pk2(a1, a1);
        s_w[tid].w2 = pk2(a2, a2);
        s_w[tid].b  = pk2(bb, bb);
        s_w2[tid].x = pk2(w2, w2);
        s_w2[tid].y = pk2(w2 * LN2, w2 * LN2);
    }
    __syncthreads();

    const float pv0 = pivot[0], pv1 = pivot[1], pv2 = pivot[2];
    const float b2v = b2[0];
    const int n_it = n_iter_p ? *n_iter_p : 20;

    const int base = (blockIdx.x * THREADS + tid) * RPT;
    const bool valid = (base + 1 < n_rays);

    float4 rv0 = valid ? reinterpret_cast<const float4*>(r)[base]
                       : make_float4(1.f, 0.f, 0.f, 0.f);
    float4 rv1 = valid ? reinterpret_cast<const float4*>(r)[base + 1]
                       : make_float4(1.f, 0.f, 0.f, 0.f);

    float inv0 = rsqrtf(rv0.x * rv0.x + rv0.y * rv0.y + rv0.z * rv0.z + rv0.w * rv0.w);
    float inv1 = rsqrtf(rv1.x * rv1.x + rv1.y * rv1.y + rv1.z * rv1.z + rv1.w * rv1.w);
    float rn0_0 = rv0.x * inv0, dx0 = rv0.y * inv0, dy0 = rv0.z * inv0, dz0 = rv0.w * inv0;
    float rn0_1 = rv1.x * inv1, dx1 = rv1.y * inv1, dy1 = rv1.z * inv1, dz1 = rv1.w * inv1;

    float alpha0 = 0.f, alpha1 = 0.f;

    // Packed poly coefficients (8 regs).
    const ull C0 = pk2(PE0, PE0), C1 = pk2(PE1, PE1),
              C2 = pk2(PE2, PE2), C3 = pk2(PE3, PE3);

    for (int it = 0; it < n_it; ++it) {
        // Sample point, packed across the 2 rays.
        ull p0d = pk2(fmaf(alpha0, dx0, pv0), fmaf(alpha1, dx1, pv0));
        ull p1d = pk2(fmaf(alpha0, dy0, pv1), fmaf(alpha1, dy1, pv1));
        ull p2d = pk2(fmaf(alpha0, dz0, pv2), fmaf(alpha1, dz1, pv2));
        float x0_0 = alpha0 * rn0_0;
        float x0_1 = alpha1 * rn0_1;

        ull accP = 0ull;   // W2 * ln(1+e)
        ull accM = 0ull;   // (W2*ln2) * max(aL, 0)

        #pragma unroll 4
        for (int j = 0; j < HIDDEN; ++j) {
            const ulonglong2* wp = reinterpret_cast<const ulonglong2*>(&s_w[j]);
            ulonglong2 q0 = wp[0];       // w0, w1
            ulonglong2 q1 = wp[1];       // w2, b
            ulonglong2 q2 = s_w2[j];     // {W2,W2}, {W2*ln2, W2*ln2}

            // aL = (x . W1 + b1) * log2e, packed over 2 rays
            ull aL = ffma2(p0d, q0.x, ffma2(p1d, q0.y, ffma2(p2d, q1.x, q1.y)));
            float alo, ahi; upk2(aL, alo, ahi);

            // e = 2^(-|aL|) = exp(-|a|), per lane (MUFU)
            float elo = ex2f_(-fabsf(alo));
            float ehi = ex2f_(-fabsf(ahi));
            ull e2 = pk2(elo, ehi);

            // ln(1+e): degree-3 Horner in e
            ull p = ffma2(C3, e2, C2);
            p = ffma2(p, e2, C1);
            p = ffma2(p, e2, C0);

            // relu part
            ull m = pk2(fmaxf(alo, 0.f), fmaxf(ahi, 0.f));

            accP = ffma2(q2.x, p, accP);
            accM = ffma2(q2.y, m, accM);
        }

        float pl, ph, ml, mh;
        upk2(accP, pl, ph);
        upk2(accM, ml, mh);
        float s0 = (pl + ml) + b2v;
        float s1 = (ph + mh) + b2v;

        float a0 = fabsf(s0);
        float a1 = fabsf(s1);
        float ext0 = fmaxf(fmaxf(s0, x0_0 - a0), -a0 - x0_0);
        float ext1 = fmaxf(fmaxf(s1, x0_1 - a1), -a1 - x0_1);
        alpha0 -= ext0;
        alpha1 -= ext1;
    }

    if (valid) {
        out[3 * base + 0] = fmaf(alpha0, dx0, pv0);
        out[3 * base + 1] = fmaf(alpha0, dy0, pv1);
        out[3 * base + 2] = fmaf(alpha0, dz0, pv2);
        out[3 * base + 3] = fmaf(alpha1, dx1, pv0);
        out[3 * base + 4] = fmaf(alpha1, dy1, pv1);
        out[3 * base + 5] = fmaf(alpha1, dz1, pv2);
    }
}

extern "C" void kernel_launch(void* const* d_in, const int* in_sizes, int n_in,
                              void* d_out, int out_size)
{
    const float* r     = (const float*)d_in[0];
    const float* pivot = (const float*)d_in[1];
    const float* W1    = (const float*)d_in[2];
    const float* b1    = (const float*)d_in[3];
    const float* W2    = (const float*)d_in[4];
    const float* b2    = (const float*)d_in[5];
    const int*   n_it  = (n_in > 6) ? (const int*)d_in[6] : nullptr;

    const int n_rays = in_sizes[0] / 4;
    const int rays_per_block = THREADS * RPT;
    const int blocks = (n_rays + rays_per_block - 1) / rays_per_block;

    raymarch_kernel<<<blocks, THREADS>>>(r, pivot, W1, b1, W2, b2, n_it,
                                         (float*)d_out, n_rays);
}